// round 7
// baseline (speedup 1.0000x reference)
#include <cuda_runtime.h>

// Shapes (fixed): O=256, I=512, K=3, C=128, B=128
// Inputs (metadata order):
//   d_in[0] x                (B=128, I=512)  f32
//   d_in[1] control_points   (O=256, 4)      f32 (unused; k=3 fixed)
//   d_in[2] control_values   (O=256, 4, C=128) f32
//   d_in[3] expansion_matrix (C=128, I=512)  f32
// Output: (O=256, B=128, T=512) f32
//
// Factorization:
//   Y[c,b]   = sum_f E[c,f] x[b,f]                (K1: 128x128x512)
//   Z[o,b,k] = sum_c cv[o,k,c] Y[c,b]             (K2: tiny)
//   out[o,b,t] = piecewise-linear in t from Z      (K3: pure affine stream)

static constexpr int C_ = 128;
static constexpr int B_ = 128;
static constexpr int I_ = 512;
static constexpr int O_ = 256;

// Scratch (static device globals — no allocation)
__device__ float  g_Y[C_ * B_];        // Y[c][b]  (b contiguous)
__device__ float4 g_Z[O_ * B_];        // Z[o*128+b] = (z0,z1,z2,z3)

// ---------------------------------------------------------------------------
// K1: Y[c][b] = dot(E[c,:], x[b,:]).  grid (16 c-tiles, 16 b-tiles), block 8x8.
// x tile staged once in padded shared (single barrier); E streamed via L1.
// ---------------------------------------------------------------------------
__global__ void __launch_bounds__(64)
y_gemm_kernel(const float* __restrict__ x, const float* __restrict__ E) {
    __shared__ float sX[8][516];   // 516-pad kills the stride-512 bank aliasing
    const int tx = threadIdx.x, ty = threadIdx.y;
    const int tid = ty * 8 + tx;

    // Stage 8 x-rows (8 x 512 floats) as float4, coalesced.
    const float4* __restrict__ x4 = (const float4*)x;
    for (int i = tid; i < 8 * 128; i += 64) {
        const int r = i >> 7, f4 = i & 127;
        *(float4*)&sX[r][f4 << 2] = x4[(blockIdx.y * 8 + r) * 128 + f4];
    }
    __syncthreads();

    const int c = blockIdx.x * 8 + tx;
    const int b = blockIdx.y * 8 + ty;
    const float4* __restrict__ Erow = (const float4*)E + c * 128;

    float acc = 0.0f;
#pragma unroll 8
    for (int f4 = 0; f4 < 128; ++f4) {
        const float4 e  = __ldg(Erow + f4);
        const float4 xv = *(const float4*)&sX[ty][f4 << 2];
        acc = fmaf(e.x, xv.x, acc);
        acc = fmaf(e.y, xv.y, acc);
        acc = fmaf(e.z, xv.z, acc);
        acc = fmaf(e.w, xv.w, acc);
    }
    g_Y[c * B_ + b] = acc;
}

// ---------------------------------------------------------------------------
// K2: Z[o,b,0..3] = sum_c cv[o,k,c] * Y[c,b].  grid 256 (o), block 128 (b).
// cv row in shared (broadcast reads), Y reads coalesced, float4 store.
// ---------------------------------------------------------------------------
__global__ void __launch_bounds__(128)
z_kernel(const float* __restrict__ cv) {
    __shared__ float scv[512];
    const int o = blockIdx.x;
    const int b = threadIdx.x;
    ((float4*)scv)[b] = ((const float4*)(cv + (size_t)o * 512))[b];
    __syncthreads();

    float a0 = 0.f, a1 = 0.f, a2 = 0.f, a3 = 0.f;
#pragma unroll 4
    for (int c = 0; c < C_; ++c) {
        const float y = g_Y[c * B_ + b];
        a0 = fmaf(scv[c],       y, a0);
        a1 = fmaf(scv[128 + c], y, a1);
        a2 = fmaf(scv[256 + c], y, a2);
        a3 = fmaf(scv[384 + c], y, a3);
    }
    g_Z[o * B_ + b] = make_float4(a0, a1, a2, a3);
}

// ---------------------------------------------------------------------------
// K3: out[rid, t] = lerp over Z[rid].  One warp per (o,b) row; each lane owns
// 16 consecutive t.  Per segment j: v(t) = (z_j - j*dz_j) + t*(h*dz_j), affine
// in t.  A lane's span crosses a knot (t=171 / t=341) at most once, so run two
// affine sequences (lo/hi) and select by a precomputed per-lane switch index.
// grid 4096 blocks x 256 threads (8 rows/block), 4 x STG.128 per lane.
// ---------------------------------------------------------------------------
__global__ void __launch_bounds__(256)
spline_write_kernel(float* __restrict__ out) {
    const int rid  = blockIdx.x * 8 + (threadIdx.x >> 5);
    const int lane = threadIdx.x & 31;

    const float4 z = g_Z[rid];                 // broadcast within warp
    const float dz0 = z.y - z.x;
    const float dz1 = z.z - z.y;
    const float dz2 = z.w - z.z;
    const float h = 3.0f / 511.0f;

    const int t0  = lane << 4;
    const int t15 = t0 + 15;
    const int jlo = (t0  >= 341) ? 2 : ((t0  >= 171) ? 1 : 0);
    const int jhi = (t15 >= 341) ? 2 : ((t15 >= 171) ? 1 : 0);

    const float s_lo = h * ((jlo == 0) ? dz0 : ((jlo == 1) ? dz1 : dz2));
    const float b_lo = (jlo == 0) ? z.x : ((jlo == 1) ? (z.y - dz1) : (z.z - 2.0f * dz2));
    const float s_hi = h * ((jhi == 0) ? dz0 : ((jhi == 1) ? dz1 : dz2));
    const float b_hi = (jhi == 0) ? z.x : ((jhi == 1) ? (z.y - dz1) : (z.z - 2.0f * dz2));

    // element index u (0..15) at which this lane switches lo -> hi
    const int swl = (jlo == jhi) ? 64 : (((jhi == 1) ? 171 : 341) - t0);

    const float tf = (float)t0;
    float vlo = fmaf(tf, s_lo, b_lo);
    float vhi = fmaf(tf, s_hi, b_hi);

    float4* __restrict__ op = (float4*)(out + (size_t)rid * 512 + t0);
#pragma unroll
    for (int q = 0; q < 4; ++q) {
        float4 r;
        r.x = ((q * 4 + 0) >= swl) ? vhi : vlo;  vlo += s_lo;  vhi += s_hi;
        r.y = ((q * 4 + 1) >= swl) ? vhi : vlo;  vlo += s_lo;  vhi += s_hi;
        r.z = ((q * 4 + 2) >= swl) ? vhi : vlo;  vlo += s_lo;  vhi += s_hi;
        r.w = ((q * 4 + 3) >= swl) ? vhi : vlo;  vlo += s_lo;  vhi += s_hi;
        op[q] = r;
    }
}

// ---------------------------------------------------------------------------
extern "C" void kernel_launch(void* const* d_in, const int* in_sizes, int n_in,
                              void* d_out, int out_size) {
    const float* x  = (const float*)d_in[0];
    const float* cv = (const float*)d_in[2];
    const float* E  = (const float*)d_in[3];
    float* out = (float*)d_out;

    y_gemm_kernel<<<dim3(16, 16), dim3(8, 8)>>>(x, E);
    z_kernel<<<O_, 128>>>(cv);
    spline_write_kernel<<<(O_ * B_) / 8, 256>>>(out);
}

// round 10
// speedup vs baseline: 1.2528x; 1.2528x over previous
#include <cuda_runtime.h>

// Shapes (fixed): O=256, I=512, K=3, C=128, B=128
// Inputs (metadata order):
//   d_in[0] x                (B=128, I=512)  f32
//   d_in[1] control_points   (O=256, 4)      f32 (unused; k=3 fixed)
//   d_in[2] control_values   (O=256, 4, C=128) f32
//   d_in[3] expansion_matrix (C=128, I=512)  f32
// Output: (O=256, B=128, T=512) f32
//
// Factorization:
//   Y[c,b]   = sum_f E[c,f] x[b,f]                (K1: warp-per-output)
//   Z[o,b,k] = sum_c cv[o,k,c] Y[c,b]             (K2: tiny)
//   out[o,b,t] = piecewise-linear in t from Z      (K3: affine stream, LTS-bound)

static constexpr int C_ = 128;
static constexpr int B_ = 128;
static constexpr int O_ = 256;

// Scratch (static device globals — no allocation)
__device__ float  g_Y[C_ * B_];        // Y[c][b]  (b contiguous)
__device__ float4 g_Z[O_ * B_];        // Z[o*128+b] = (z0,z1,z2,z3)

// ---------------------------------------------------------------------------
// K1: warp-per-output Y[c][b] = dot(E[c,:], x[b,:]).
// Lanes split f: lane l handles float4 elements l, l+32, l+64, l+96 (coalesced).
// Block = 1024 threads = 32 warps = 4c x 8b tile (L1 reuse of both rows).
// grid (32, 16).
// ---------------------------------------------------------------------------
__global__ void __launch_bounds__(1024)
y_gemm_kernel(const float* __restrict__ x, const float* __restrict__ E) {
    const int w    = threadIdx.x >> 5;
    const int lane = threadIdx.x & 31;
    const int c = blockIdx.x * 4 + (w >> 3);
    const int b = blockIdx.y * 8 + (w & 7);

    const float4* __restrict__ E4 = (const float4*)E + c * 128 + lane;
    const float4* __restrict__ x4 = (const float4*)x + b * 128 + lane;

    float4 a0 = make_float4(0.f, 0.f, 0.f, 0.f);
    float4 a1 = make_float4(0.f, 0.f, 0.f, 0.f);
#pragma unroll
    for (int i = 0; i < 4; i += 2) {
        const float4 e0 = E4[32 * i],     xv0 = x4[32 * i];
        const float4 e1 = E4[32 * i + 32], xv1 = x4[32 * i + 32];
        a0.x = fmaf(e0.x, xv0.x, a0.x);  a0.y = fmaf(e0.y, xv0.y, a0.y);
        a0.z = fmaf(e0.z, xv0.z, a0.z);  a0.w = fmaf(e0.w, xv0.w, a0.w);
        a1.x = fmaf(e1.x, xv1.x, a1.x);  a1.y = fmaf(e1.y, xv1.y, a1.y);
        a1.z = fmaf(e1.z, xv1.z, a1.z);  a1.w = fmaf(e1.w, xv1.w, a1.w);
    }
    float s = ((a0.x + a1.x) + (a0.y + a1.y)) + ((a0.z + a1.z) + (a0.w + a1.w));
#pragma unroll
    for (int off = 16; off > 0; off >>= 1)
        s += __shfl_down_sync(0xFFFFFFFFu, s, off);
    if (lane == 0) g_Y[c * B_ + b] = s;
}

// ---------------------------------------------------------------------------
// K2: Z[o,b,0..3] = sum_c cv[o,k,c] * Y[c,b].  grid 256 (o), block 128 (b).
// cv row in shared (broadcast reads), Y reads coalesced, float4 store.
// ---------------------------------------------------------------------------
__global__ void __launch_bounds__(128)
z_kernel(const float* __restrict__ cv) {
    __shared__ float scv[512];
    const int o = blockIdx.x;
    const int b = threadIdx.x;
    ((float4*)scv)[b] = ((const float4*)(cv + (size_t)o * 512))[b];
    __syncthreads();

    float a0 = 0.f, a1 = 0.f, a2 = 0.f, a3 = 0.f;
#pragma unroll 4
    for (int c = 0; c < C_; ++c) {
        const float y = g_Y[c * B_ + b];
        a0 = fmaf(scv[c],       y, a0);
        a1 = fmaf(scv[128 + c], y, a1);
        a2 = fmaf(scv[256 + c], y, a2);
        a3 = fmaf(scv[384 + c], y, a3);
    }
    g_Z[o * B_ + b] = make_float4(a0, a1, a2, a3);
}

// ---------------------------------------------------------------------------
// K3: out[rid, t] piecewise-linear from Z[rid].  One warp per (o,b) row; lane
// owns 16 consecutive t.  v(t) = (z_j - j*dz_j) + t*(h*dz_j) per segment; a
// lane's span crosses a knot at most once -> two affine sequences + select.
// grid 4096 x 256 (8 rows/block), 4 x STG.128 per lane.
// ---------------------------------------------------------------------------
__global__ void __launch_bounds__(256)
spline_write_kernel(float* __restrict__ out) {
    const int rid  = blockIdx.x * 8 + (threadIdx.x >> 5);
    const int lane = threadIdx.x & 31;

    const float4 z = g_Z[rid];
    const float dz0 = z.y - z.x;
    const float dz1 = z.z - z.y;
    const float dz2 = z.w - z.z;
    const float h = 3.0f / 511.0f;

    const int t0  = lane << 4;
    const int t15 = t0 + 15;
    const int jlo = (t0  >= 341) ? 2 : ((t0  >= 171) ? 1 : 0);
    const int jhi = (t15 >= 341) ? 2 : ((t15 >= 171) ? 1 : 0);

    const float s_lo = h * ((jlo == 0) ? dz0 : ((jlo == 1) ? dz1 : dz2));
    const float b_lo = (jlo == 0) ? z.x : ((jlo == 1) ? (z.y - dz1) : (z.z - 2.0f * dz2));
    const float s_hi = h * ((jhi == 0) ? dz0 : ((jhi == 1) ? dz1 : dz2));
    const float b_hi = (jhi == 0) ? z.x : ((jhi == 1) ? (z.y - dz1) : (z.z - 2.0f * dz2));

    const int swl = (jlo == jhi) ? 64 : (((jhi == 1) ? 171 : 341) - t0);

    const float tf = (float)t0;
    float vlo = fmaf(tf, s_lo, b_lo);
    float vhi = fmaf(tf, s_hi, b_hi);

    float4* __restrict__ op = (float4*)(out + (size_t)rid * 512 + t0);
#pragma unroll
    for (int q = 0; q < 4; ++q) {
        float4 r;
        r.x = ((q * 4 + 0) >= swl) ? vhi : vlo;  vlo += s_lo;  vhi += s_hi;
        r.y = ((q * 4 + 1) >= swl) ? vhi : vlo;  vlo += s_lo;  vhi += s_hi;
        r.z = ((q * 4 + 2) >= swl) ? vhi : vlo;  vlo += s_lo;  vhi += s_hi;
        r.w = ((q * 4 + 3) >= swl) ? vhi : vlo;  vlo += s_lo;  vhi += s_hi;
        op[q] = r;
    }
}

// ---------------------------------------------------------------------------
extern "C" void kernel_launch(void* const* d_in, const int* in_sizes, int n_in,
                              void* d_out, int out_size) {
    const float* x  = (const float*)d_in[0];
    const float* cv = (const float*)d_in[2];
    const float* E  = (const float*)d_in[3];
    float* out = (float*)d_out;

    y_gemm_kernel<<<dim3(32, 16), 1024>>>(x, E);
    z_kernel<<<O_, 128>>>(cv);
    spline_write_kernel<<<(O_ * B_) / 8, 256>>>(out);
}

// round 15
// speedup vs baseline: 1.7099x; 1.3649x over previous
#include <cuda_runtime.h>

// Shapes (fixed): O=256, I=512, K=3, C=128, B=128
// Inputs (metadata order):
//   d_in[0] x                (B=128, I=512)  f32
//   d_in[1] control_points   (O=256, 4)      f32 (unused; k=3 fixed)
//   d_in[2] control_values   (O=256, 4, C=128) f32
//   d_in[3] expansion_matrix (C=128, I=512)  f32
// Output: (O=256, B=128, T=512) f32
//
//   Yt[b,c]  = sum_f E[c,f] x[b,f]                    (K1)
//   Z[o,b,k] = sum_c cv[o,k,c] Yt[b,c]   } fused      (K3 prologue)
//   out[o,b,t] = piecewise-linear in t   } one kernel (K3 write phase)

static constexpr int C_ = 128;
static constexpr int B_ = 128;
static constexpr int O_ = 256;

// Scratch (static device global — no allocation). b-major for K3 prologue.
__device__ float g_Yt[B_ * C_];

// ---------------------------------------------------------------------------
// K1: warp-per-output Yt[b][c] = dot(E[c,:], x[b,:]).
// Lane l reads float4 elements l, l+32, l+64, l+96 (coalesced), shuffle-reduce.
// Block = 512 threads = 16 warps = 4c x 4b tile (L1 reuse); grid (32, 32).
// 3 blocks/SM resident -> deep latency hiding, no wave quantization cliff.
// ---------------------------------------------------------------------------
__global__ void __launch_bounds__(512)
y_gemm_kernel(const float* __restrict__ x, const float* __restrict__ E) {
    const int w    = threadIdx.x >> 5;
    const int lane = threadIdx.x & 31;
    const int c = blockIdx.x * 4 + (w >> 2);
    const int b = blockIdx.y * 4 + (w & 3);

    const float4* __restrict__ E4 = (const float4*)E + c * 128 + lane;
    const float4* __restrict__ x4 = (const float4*)x + b * 128 + lane;

    const float4 e0 = E4[0],  xv0 = x4[0];
    const float4 e1 = E4[32], xv1 = x4[32];
    const float4 e2 = E4[64], xv2 = x4[64];
    const float4 e3 = E4[96], xv3 = x4[96];

    float4 a0, a1;
    a0.x = e0.x * xv0.x; a0.y = e0.y * xv0.y; a0.z = e0.z * xv0.z; a0.w = e0.w * xv0.w;
    a1.x = e1.x * xv1.x; a1.y = e1.y * xv1.y; a1.z = e1.z * xv1.z; a1.w = e1.w * xv1.w;
    a0.x = fmaf(e2.x, xv2.x, a0.x); a0.y = fmaf(e2.y, xv2.y, a0.y);
    a0.z = fmaf(e2.z, xv2.z, a0.z); a0.w = fmaf(e2.w, xv2.w, a0.w);
    a1.x = fmaf(e3.x, xv3.x, a1.x); a1.y = fmaf(e3.y, xv3.y, a1.y);
    a1.z = fmaf(e3.z, xv3.z, a1.z); a1.w = fmaf(e3.w, xv3.w, a1.w);

    float s = ((a0.x + a1.x) + (a0.y + a1.y)) + ((a0.z + a1.z) + (a0.w + a1.w));
#pragma unroll
    for (int off = 16; off > 0; off >>= 1)
        s += __shfl_down_sync(0xFFFFFFFFu, s, off);
    if (lane == 0) g_Yt[b * C_ + c] = s;
}

// ---------------------------------------------------------------------------
// K3 (fused Z + write): grid 4096 x 256. Block covers one o and 8 b's.
// Prologue: stage cv[o] (padded smem, conflict-free) + 8 Yt rows; each warp w
// computes z[k] for its row via lane=(k,chunk) split: c = chunk + 8*i, smem
// bank = (k*8 + chunk + 8i) mod 32 — a perfect permutation, zero conflicts.
// Write phase: two affine sequences (lo/hi) + per-lane knot-switch select,
// 4 x STG.128 per lane.
// ---------------------------------------------------------------------------
__global__ void __launch_bounds__(256)
spline_fused_kernel(const float* __restrict__ cv, float* __restrict__ out) {
    __shared__ float scv[4 * 136];     // cv[o][k][c] at scv[k*136 + c]
    __shared__ float sYt[8 * 128];     // Yt rows for this block's 8 b's

    const int bid = blockIdx.x;
    const int o      = bid >> 4;
    const int bgroup = bid & 15;
    const int tid  = threadIdx.x;
    const int w    = tid >> 5;         // warp = local row (b_local)
    const int lane = tid & 31;

    // Stage cv row (512 floats, 2 per thread -> padded layout)
    {
        const int e = tid * 2;                     // 0..510, even
        const int k = e >> 7, c = e & 127;
        const float2 v = *(const float2*)(cv + (size_t)o * 512 + e);
        scv[k * 136 + c]     = v.x;
        scv[k * 136 + c + 1] = v.y;
    }
    // Stage 8 Yt rows (1024 floats = 256 float4, 1 per thread)
    {
        const int bl = tid >> 5, c4 = tid & 31;
        const float4 v = *(const float4*)(g_Yt + (bgroup * 8 + bl) * C_ + c4 * 4);
        *(float4*)&sYt[bl * 128 + c4 * 4] = v;
    }
    __syncthreads();

    // z-dots: lane = k*8 + chunk; c = chunk + 8*i
    const int k     = lane >> 3;
    const int chunk = lane & 7;
    const float* __restrict__ cvk = scv + k * 136 + chunk;
    const float* __restrict__ yr  = sYt + w * 128 + chunk;
    float p = 0.0f;
#pragma unroll
    for (int i = 0; i < 16; ++i)
        p = fmaf(cvk[8 * i], yr[8 * i], p);
    // segmented 8-lane reduce -> z[k] at lane k*8
    p += __shfl_down_sync(0xFFFFFFFFu, p, 4, 8);
    p += __shfl_down_sync(0xFFFFFFFFu, p, 2, 8);
    p += __shfl_down_sync(0xFFFFFFFFu, p, 1, 8);
    const float z0 = __shfl_sync(0xFFFFFFFFu, p, 0);
    const float z1 = __shfl_sync(0xFFFFFFFFu, p, 8);
    const float z2 = __shfl_sync(0xFFFFFFFFu, p, 16);
    const float z3 = __shfl_sync(0xFFFFFFFFu, p, 24);

    // ---- write phase: piecewise-linear stream over t = 0..511 ----
    const float dz0 = z1 - z0;
    const float dz1 = z2 - z1;
    const float dz2 = z3 - z2;
    const float h = 3.0f / 511.0f;

    const int t0  = lane << 4;
    const int t15 = t0 + 15;
    const int jlo = (t0  >= 341) ? 2 : ((t0  >= 171) ? 1 : 0);
    const int jhi = (t15 >= 341) ? 2 : ((t15 >= 171) ? 1 : 0);

    const float s_lo = h * ((jlo == 0) ? dz0 : ((jlo == 1) ? dz1 : dz2));
    const float b_lo = (jlo == 0) ? z0 : ((jlo == 1) ? (z1 - dz1) : (z2 - 2.0f * dz2));
    const float s_hi = h * ((jhi == 0) ? dz0 : ((jhi == 1) ? dz1 : dz2));
    const float b_hi = (jhi == 0) ? z0 : ((jhi == 1) ? (z1 - dz1) : (z2 - 2.0f * dz2));

    const int swl = (jlo == jhi) ? 64 : (((jhi == 1) ? 171 : 341) - t0);

    const float tf = (float)t0;
    float vlo = fmaf(tf, s_lo, b_lo);
    float vhi = fmaf(tf, s_hi, b_hi);

    const int rid = o * B_ + bgroup * 8 + w;
    float4* __restrict__ op = (float4*)(out + (size_t)rid * 512 + t0);
#pragma unroll
    for (int q = 0; q < 4; ++q) {
        float4 r;
        r.x = ((q * 4 + 0) >= swl) ? vhi : vlo;  vlo += s_lo;  vhi += s_hi;
        r.y = ((q * 4 + 1) >= swl) ? vhi : vlo;  vlo += s_lo;  vhi += s_hi;
        r.z = ((q * 4 + 2) >= swl) ? vhi : vlo;  vlo += s_lo;  vhi += s_hi;
        r.w = ((q * 4 + 3) >= swl) ? vhi : vlo;  vlo += s_lo;  vhi += s_hi;
        op[q] = r;
    }
}

// ---------------------------------------------------------------------------
extern "C" void kernel_launch(void* const* d_in, const int* in_sizes, int n_in,
                              void* d_out, int out_size) {
    const float* x  = (const float*)d_in[0];
    const float* cv = (const float*)d_in[2];
    const float* E  = (const float*)d_in[3];
    float* out = (float*)d_out;

    y_gemm_kernel<<<dim3(32, 32), 512>>>(x, E);
    spline_fused_kernel<<<(O_ * B_) / 8, 256>>>(cv, out);
}